// round 1
// baseline (speedup 1.0000x reference)
#include <cuda_runtime.h>

#define NP 16      // B*K problems
#define N  2048    // points per cloud

// ---------------- scratch (__device__ globals: allocation-free) ----------------
__device__ float4 g_Xs[NP][N];            // scaled points + squared norm
__device__ float  g_deg[NP][N];           // row degree of thresholded W
__device__ float  g_PT[NP][N][N];         // PT[p][j][i] = P[i][j]  (transposed!)
__device__ float  g_c1[17][NP][N * 4];    // bank-1 chain, 3 cols + zero pad
__device__ float  g_c2[17][NP][N * 16];   // bank-2 chain, 15 cols + zero pad

// ---------------- helpers ----------------
__device__ __forceinline__ unsigned long long pack2(float a) {
    unsigned long long r;
    asm("mov.b64 %0, {%1, %1};" : "=l"(r) : "f"(a));
    return r;
}
__device__ __forceinline__ void fma2(unsigned long long& d, unsigned long long a,
                                     unsigned long long b) {
    asm("fma.rn.f32x2 %0, %1, %2, %0;" : "+l"(d) : "l"(a), "l"(b));
}
__device__ __forceinline__ float warpSum(float v) {
#pragma unroll
    for (int o = 16; o; o >>= 1) v += __shfl_xor_sync(0xffffffffu, v, o);
    return v;
}

// ---------------- 1. scale points, init chain-1 state ----------------
__global__ void prepK(const float* __restrict__ pc, const float* __restrict__ al) {
    int idx = blockIdx.x * blockDim.x + threadIdx.x;
    if (idx >= NP * N) return;
    int p = idx / N, i = idx - p * N;
    int b = p >> 2, k = p & 3;
    const float* xp = pc + ((size_t)b * N + i) * 3;
    float x = xp[0] * al[k * 3 + 0];
    float y = xp[1] * al[k * 3 + 1];
    float z = xp[2] * al[k * 3 + 2];
    g_Xs[p][i] = make_float4(x, y, z, x * x + y * y + z * z);
    float* c0 = &g_c1[0][p][i * 4];
    c0[0] = x; c0[1] = y; c0[2] = z; c0[3] = 0.f;
}

// ---------------- 2. degrees (row sums of thresholded W) ----------------
__global__ void degK() {
    int r = blockIdx.x * 8 + (threadIdx.x >> 5);   // one warp per row
    int lane = threadIdx.x & 31;
    int p = r / N, i = r - p * N;
    float4 xi = g_Xs[p][i];
    float s = 0.f;
    for (int j = lane; j < N; j += 32) {
        float4 xj = g_Xs[p][j];
        float d = xi.w + xj.w - 2.f * (xi.x * xj.x + xi.y * xj.y + xi.z * xj.z);
        float w = __expf(-d * 0.1f);
        s += (w < 0.1f) ? 0.f : w;
    }
    s = warpSum(s);
    if (lane == 0) g_deg[p][i] = s;
}

// ---------------- 3. build transposed lazy-walk matrix ----------------
// P[i][j] = 0.5*(delta_ij + W_ij/deg_i);  stored as PT[p][j][i] (i fastest).
__global__ void buildK() {
    int p = blockIdx.z;
    int i = blockIdx.x * 256 + threadIdx.x;
    int j0 = blockIdx.y * 8;
    float4 xi = g_Xs[p][i];
    float rd = 0.5f / g_deg[p][i];
#pragma unroll
    for (int jj = 0; jj < 8; jj++) {
        int j = j0 + jj;
        float4 xj = g_Xs[p][j];
        float d = xi.w + xj.w - 2.f * (xi.x * xj.x + xi.y * xj.y + xi.z * xj.z);
        float w = __expf(-d * 0.1f);
        w = (w < 0.1f) ? 0.f : w;
        g_PT[p][j][i] = w * rd + ((i == j) ? 0.5f : 0.f);
    }
}

// ---------------- 4. apply kernel: next = P @ cur ----------------
// Stationary-output GEMV against transposed P. Each thread owns 2 rows,
// accumulates CP columns in packed f32x2 registers (FFMA2). cur[j] comes
// from SMEM as a warp-wide broadcast.
template <int CP>
__global__ void __launch_bounds__(128) applyK(int sSrc, int sDst) {
    constexpr int CH = 512;
    __shared__ __align__(16) float sc[CH * CP];
    int p = blockIdx.y;
    const float* srcBase = (CP == 4) ? &g_c1[sSrc][0][0] : &g_c2[sSrc][0][0];
    float*       dstBase = (CP == 4) ? &g_c1[sDst][0][0] : &g_c2[sDst][0][0];
    const float* PTp  = &g_PT[p][0][0];
    const float* curp = srcBase + (size_t)p * N * CP;
    int i0 = blockIdx.x * 256 + threadIdx.x * 2;

    unsigned long long a0[CP / 2], a1[CP / 2];
#pragma unroll
    for (int c = 0; c < CP / 2; c++) { a0[c] = 0ull; a1[c] = 0ull; }

    for (int j0 = 0; j0 < N; j0 += CH) {
        __syncthreads();
        {   // stage cur chunk into SMEM (coalesced float4)
            const float4* s4 = (const float4*)(curp + (size_t)j0 * CP);
            float4* d4 = (float4*)sc;
            for (int t = threadIdx.x; t < CH * CP / 4; t += 128) d4[t] = s4[t];
        }
        __syncthreads();
#pragma unroll 4
        for (int j = 0; j < CH; j++) {
            float2 pv = *(const float2*)(PTp + (size_t)(j0 + j) * N + i0);
            unsigned long long px = pack2(pv.x), py = pack2(pv.y);
            const unsigned long long* cs = (const unsigned long long*)(sc + j * CP);
#pragma unroll
            for (int c = 0; c < CP / 2; c++) {
                unsigned long long cv = cs[c];
                fma2(a0[c], px, cv);
                fma2(a1[c], py, cv);
            }
        }
    }
    float* o0 = dstBase + ((size_t)p * N + i0) * CP;
#pragma unroll
    for (int c = 0; c < CP / 2; c++) {
        float x0, y0, x1, y1;
        asm("mov.b64 {%0, %1}, %2;" : "=f"(x0), "=f"(y0) : "l"(a0[c]));
        asm("mov.b64 {%0, %1}, %2;" : "=f"(x1), "=f"(y1) : "l"(a1[c]));
        o0[2 * c] = x0; o0[2 * c + 1] = y0;
        o0[CP + 2 * c] = x1; o0[CP + 2 * c + 1] = y1;
    }
}

// ---------------- 5. first-order features + build U + partial output ----------------
__global__ void midK(float* __restrict__ out) {
    int p = blockIdx.x, tid = threadIdx.x;
    float ls[18];
#pragma unroll
    for (int v = 0; v < 18; v++) ls[v] = 0.f;
    for (int i = tid; i < N; i += 256) {
        const float* L0  = &g_c1[0][p][i * 4];
        const float* L1  = &g_c1[1][p][i * 4];
        const float* L2  = &g_c1[2][p][i * 4];
        const float* L4  = &g_c1[4][p][i * 4];
        const float* L8  = &g_c1[8][p][i * 4];
        const float* L16 = &g_c1[16][p][i * 4];
        float* U = &g_c2[0][p][i * 16];
#pragma unroll
        for (int c = 0; c < 3; c++) {
            float u0 = fabsf(L0[c] - L1[c]);
            float u1 = fabsf(L1[c] - L2[c]);
            float u2 = fabsf(L2[c] - L4[c]);
            float u3 = fabsf(L4[c] - L8[c]);
            float u4 = fabsf(L8[c] - L16[c]);
            U[c] = u0; U[3 + c] = u1; U[6 + c] = u2; U[9 + c] = u3; U[12 + c] = u4;
            ls[c]      += L16[c];
            ls[3 + c]  += u0;  ls[6 + c]  += u1;  ls[9 + c]  += u2;
            ls[12 + c] += u3;  ls[15 + c] += u4;
        }
        U[15] = 0.f;
    }
    __shared__ float red[18][8];
    int wid = tid >> 5, lane = tid & 31;
#pragma unroll
    for (int v = 0; v < 18; v++) {
        float s = warpSum(ls[v]);
        if (lane == 0) red[v][wid] = s;
    }
    __syncthreads();
    if (tid < 18) {
        float s = 0.f;
#pragma unroll
        for (int w = 0; w < 8; w++) s += red[tid][w];
        int b = p >> 2, k = p & 3;
        out[b * 192 + k * 48 + tid] = s * (1.f / 2048.f);
    }
}

// ---------------- 6. second-order features + remaining output ----------------
__global__ void finalK(float* __restrict__ out) {
    int p = blockIdx.x, tid = threadIdx.x;
    float ls[30];
#pragma unroll
    for (int v = 0; v < 30; v++) ls[v] = 0.f;
    for (int i = tid; i < N; i += 256) {
        const float* A1  = &g_c2[1][p][i * 16];
        const float* A2  = &g_c2[2][p][i * 16];
        const float* A4  = &g_c2[4][p][i * 16];
        const float* A8  = &g_c2[8][p][i * 16];
        const float* A16 = &g_c2[16][p][i * 16];
#pragma unroll
        for (int c = 0; c < 3;  c++) ls[c]      += fabsf(A1[c]  - A2[c]);
#pragma unroll
        for (int c = 0; c < 6;  c++) ls[3 + c]  += fabsf(A2[c]  - A4[c]);
#pragma unroll
        for (int c = 0; c < 9;  c++) ls[9 + c]  += fabsf(A4[c]  - A8[c]);
#pragma unroll
        for (int c = 0; c < 12; c++) ls[18 + c] += fabsf(A8[c]  - A16[c]);
    }
    __shared__ float red[30][8];
    int wid = tid >> 5, lane = tid & 31;
#pragma unroll
    for (int v = 0; v < 30; v++) {
        float s = warpSum(ls[v]);
        if (lane == 0) red[v][wid] = s;
    }
    __syncthreads();
    if (tid < 30) {
        float s = 0.f;
#pragma unroll
        for (int w = 0; w < 8; w++) s += red[tid][w];
        int b = p >> 2, k = p & 3;
        out[b * 192 + k * 48 + 18 + tid] = s * (1.f / 2048.f);
    }
}

// ---------------- launch ----------------
extern "C" void kernel_launch(void* const* d_in, const int* in_sizes, int n_in,
                              void* d_out, int out_size) {
    (void)in_sizes; (void)n_in; (void)out_size;
    const float* pc = (const float*)d_in[0];   // [4,2048,3]
    const float* al = (const float*)d_in[1];   // [4,3]
    float* out = (float*)d_out;                // [768]

    prepK<<<(NP * N + 255) / 256, 256>>>(pc, al);
    degK<<<NP * N / 8, 256>>>();
    buildK<<<dim3(N / 256, N / 8, NP), 256>>>();

    for (int s = 1; s <= 16; s++)
        applyK<4><<<dim3(N / 256, NP), 128>>>(s - 1, s);

    midK<<<NP, 256>>>(out);

    for (int s = 1; s <= 16; s++)
        applyK<16><<<dim3(N / 256, NP), 128>>>(s - 1, s);

    finalK<<<NP, 256>>>(out);
}

// round 2
// speedup vs baseline: 5.1377x; 5.1377x over previous
#include <cuda_runtime.h>

#define NP 16      // B*K problems
#define N  2048    // points per cloud

// ---------------- scratch (__device__ globals: allocation-free) ----------------
__device__ float4 g_Xs[NP][N];            // scaled points + squared norm
__device__ float  g_deg[NP][N];           // row degree of thresholded W
__device__ float  g_PT[NP][N][N];         // PT[p][j][i] = P[i][j]  (transposed!)
__device__ float  g_c1[17][NP][N * 4];    // bank-1 chain, 3 cols + zero pad
__device__ float  g_c2[17][NP][N * 16];   // bank-2 chain, 15 cols + zero pad
__device__ float  g_part[8][NP * N * 16]; // j-split partial accumulators

// ---------------- helpers ----------------
__device__ __forceinline__ unsigned long long pack2(float a) {
    unsigned long long r;
    asm("mov.b64 %0, {%1, %1};" : "=l"(r) : "f"(a));
    return r;
}
__device__ __forceinline__ void fma2(unsigned long long& d, unsigned long long a,
                                     unsigned long long b) {
    asm("fma.rn.f32x2 %0, %1, %2, %0;" : "+l"(d) : "l"(a), "l"(b));
}
__device__ __forceinline__ float warpSum(float v) {
#pragma unroll
    for (int o = 16; o; o >>= 1) v += __shfl_xor_sync(0xffffffffu, v, o);
    return v;
}

// ---------------- 1. scale points, init chain-1 state ----------------
__global__ void prepK(const float* __restrict__ pc, const float* __restrict__ al) {
    int idx = blockIdx.x * blockDim.x + threadIdx.x;
    if (idx >= NP * N) return;
    int p = idx / N, i = idx - p * N;
    int b = p >> 2, k = p & 3;
    const float* xp = pc + ((size_t)b * N + i) * 3;
    float x = xp[0] * al[k * 3 + 0];
    float y = xp[1] * al[k * 3 + 1];
    float z = xp[2] * al[k * 3 + 2];
    g_Xs[p][i] = make_float4(x, y, z, x * x + y * y + z * z);
    float* c0 = &g_c1[0][p][i * 4];
    c0[0] = x; c0[1] = y; c0[2] = z; c0[3] = 0.f;
}

// ---------------- 2. degrees (row sums of thresholded W) ----------------
__global__ void degK() {
    int r = blockIdx.x * 8 + (threadIdx.x >> 5);   // one warp per row
    int lane = threadIdx.x & 31;
    int p = r / N, i = r - p * N;
    float4 xi = g_Xs[p][i];
    float s = 0.f;
    for (int j = lane; j < N; j += 32) {
        float4 xj = g_Xs[p][j];
        float d = xi.w + xj.w - 2.f * (xi.x * xj.x + xi.y * xj.y + xi.z * xj.z);
        float w = __expf(-d * 0.1f);
        s += (w < 0.1f) ? 0.f : w;
    }
    s = warpSum(s);
    if (lane == 0) g_deg[p][i] = s;
}

// ---------------- 3. build transposed lazy-walk matrix ----------------
// P[i][j] = 0.5*(delta_ij + W_ij/deg_i);  stored as PT[p][j][i] (i fastest).
__global__ void buildK() {
    int p = blockIdx.z;
    int i = blockIdx.x * 256 + threadIdx.x;
    int j0 = blockIdx.y * 8;
    float4 xi = g_Xs[p][i];
    float rd = 0.5f / g_deg[p][i];
#pragma unroll
    for (int jj = 0; jj < 8; jj++) {
        int j = j0 + jj;
        float4 xj = g_Xs[p][j];
        float d = xi.w + xj.w - 2.f * (xi.x * xj.x + xi.y * xj.y + xi.z * xj.z);
        float w = __expf(-d * 0.1f);
        w = (w < 0.1f) ? 0.f : w;
        g_PT[p][j][i] = w * rd + ((i == j) ? 0.5f : 0.f);
    }
}

// ---------------- 4. apply kernel: partial of next = P @ cur over a j-chunk ----
// Grid: (i-chunks=4, j-chunks=8, problems=16). Block 256. Thread owns 2 rows,
// CP packed-f32x2 accumulators. cur[j] broadcast from SMEM. P streamed __ldcs.
template <int CP>
__global__ void __launch_bounds__(256) applyK(int sSrc) {
    constexpr int JCH = N / 8;                 // 256 j per chunk
    __shared__ __align__(16) float sc[JCH * CP];
    int p  = blockIdx.z;
    int jb = blockIdx.y * JCH;
    int i0 = blockIdx.x * 512 + threadIdx.x * 2;

    const float* srcBase = (CP == 4) ? &g_c1[sSrc][0][0] : &g_c2[sSrc][0][0];
    const float* curp = srcBase + (size_t)p * N * CP;
    const float* PTp  = &g_PT[p][0][0] + (size_t)jb * N;

    {   // stage cur chunk into SMEM (coalesced float4)
        const float4* s4 = (const float4*)(curp + (size_t)jb * CP);
        float4* d4 = (float4*)sc;
#pragma unroll
        for (int t = threadIdx.x; t < JCH * CP / 4; t += 256) d4[t] = s4[t];
    }
    __syncthreads();

    unsigned long long a0[CP / 2], a1[CP / 2];
#pragma unroll
    for (int c = 0; c < CP / 2; c++) { a0[c] = 0ull; a1[c] = 0ull; }

#pragma unroll 8
    for (int j = 0; j < JCH; j++) {
        float2 pv = __ldcs((const float2*)(PTp + (size_t)j * N + i0));
        unsigned long long px = pack2(pv.x), py = pack2(pv.y);
        const unsigned long long* cs = (const unsigned long long*)(sc + j * CP);
#pragma unroll
        for (int c = 0; c < CP / 2; c++) {
            unsigned long long cv = cs[c];
            fma2(a0[c], px, cv);
            fma2(a1[c], py, cv);
        }
    }

    float* o0 = &g_part[blockIdx.y][0] + ((size_t)p * N + i0) * CP;
#pragma unroll
    for (int c = 0; c < CP / 2; c++) {
        float x0, y0, x1, y1;
        asm("mov.b64 {%0, %1}, %2;" : "=f"(x0), "=f"(y0) : "l"(a0[c]));
        asm("mov.b64 {%0, %1}, %2;" : "=f"(x1), "=f"(y1) : "l"(a1[c]));
        o0[2 * c] = x0; o0[2 * c + 1] = y0;
        o0[CP + 2 * c] = x1; o0[CP + 2 * c + 1] = y1;
    }
}

// ---------------- 5. reduce partials into chain slot (fixed order: deterministic) ----
template <int CP>
__global__ void reduceK(int sDst) {
    float* dstBase = (CP == 4) ? &g_c1[sDst][0][0] : &g_c2[sDst][0][0];
    int idx = blockIdx.x * blockDim.x + threadIdx.x;     // float4 index
    int tot = NP * N * CP / 4;
    if (idx >= tot) return;
    float4 s = ((const float4*)&g_part[0][0])[idx];
#pragma unroll
    for (int jc = 1; jc < 8; jc++) {
        float4 v = ((const float4*)&g_part[jc][0])[idx];
        s.x += v.x; s.y += v.y; s.z += v.z; s.w += v.w;
    }
    ((float4*)dstBase)[idx] = s;
}

// ---------------- 6. first-order features + build U + partial output ----------------
__global__ void midK(float* __restrict__ out) {
    int p = blockIdx.x, tid = threadIdx.x;
    float ls[18];
#pragma unroll
    for (int v = 0; v < 18; v++) ls[v] = 0.f;
    for (int i = tid; i < N; i += 256) {
        const float* L0  = &g_c1[0][p][i * 4];
        const float* L1  = &g_c1[1][p][i * 4];
        const float* L2  = &g_c1[2][p][i * 4];
        const float* L4  = &g_c1[4][p][i * 4];
        const float* L8  = &g_c1[8][p][i * 4];
        const float* L16 = &g_c1[16][p][i * 4];
        float* U = &g_c2[0][p][i * 16];
#pragma unroll
        for (int c = 0; c < 3; c++) {
            float u0 = fabsf(L0[c] - L1[c]);
            float u1 = fabsf(L1[c] - L2[c]);
            float u2 = fabsf(L2[c] - L4[c]);
            float u3 = fabsf(L4[c] - L8[c]);
            float u4 = fabsf(L8[c] - L16[c]);
            U[c] = u0; U[3 + c] = u1; U[6 + c] = u2; U[9 + c] = u3; U[12 + c] = u4;
            ls[c]      += L16[c];
            ls[3 + c]  += u0;  ls[6 + c]  += u1;  ls[9 + c]  += u2;
            ls[12 + c] += u3;  ls[15 + c] += u4;
        }
        U[15] = 0.f;
    }
    __shared__ float red[18][8];
    int wid = tid >> 5, lane = tid & 31;
#pragma unroll
    for (int v = 0; v < 18; v++) {
        float s = warpSum(ls[v]);
        if (lane == 0) red[v][wid] = s;
    }
    __syncthreads();
    if (tid < 18) {
        float s = 0.f;
#pragma unroll
        for (int w = 0; w < 8; w++) s += red[tid][w];
        int b = p >> 2, k = p & 3;
        out[b * 192 + k * 48 + tid] = s * (1.f / 2048.f);
    }
}

// ---------------- 7. second-order features + remaining output ----------------
__global__ void finalK(float* __restrict__ out) {
    int p = blockIdx.x, tid = threadIdx.x;
    float ls[30];
#pragma unroll
    for (int v = 0; v < 30; v++) ls[v] = 0.f;
    for (int i = tid; i < N; i += 256) {
        const float* A1  = &g_c2[1][p][i * 16];
        const float* A2  = &g_c2[2][p][i * 16];
        const float* A4  = &g_c2[4][p][i * 16];
        const float* A8  = &g_c2[8][p][i * 16];
        const float* A16 = &g_c2[16][p][i * 16];
#pragma unroll
        for (int c = 0; c < 3;  c++) ls[c]      += fabsf(A1[c]  - A2[c]);
#pragma unroll
        for (int c = 0; c < 6;  c++) ls[3 + c]  += fabsf(A2[c]  - A4[c]);
#pragma unroll
        for (int c = 0; c < 9;  c++) ls[9 + c]  += fabsf(A4[c]  - A8[c]);
#pragma unroll
        for (int c = 0; c < 12; c++) ls[18 + c] += fabsf(A8[c]  - A16[c]);
    }
    __shared__ float red[30][8];
    int wid = tid >> 5, lane = tid & 31;
#pragma unroll
    for (int v = 0; v < 30; v++) {
        float s = warpSum(ls[v]);
        if (lane == 0) red[v][wid] = s;
    }
    __syncthreads();
    if (tid < 30) {
        float s = 0.f;
#pragma unroll
        for (int w = 0; w < 8; w++) s += red[tid][w];
        int b = p >> 2, k = p & 3;
        out[b * 192 + k * 48 + 18 + tid] = s * (1.f / 2048.f);
    }
}

// ---------------- launch ----------------
extern "C" void kernel_launch(void* const* d_in, const int* in_sizes, int n_in,
                              void* d_out, int out_size) {
    (void)in_sizes; (void)n_in; (void)out_size;
    const float* pc = (const float*)d_in[0];   // [4,2048,3]
    const float* al = (const float*)d_in[1];   // [4,3]
    float* out = (float*)d_out;                // [768]

    prepK<<<(NP * N + 255) / 256, 256>>>(pc, al);
    degK<<<NP * N / 8, 256>>>();
    buildK<<<dim3(N / 256, N / 8, NP), 256>>>();

    for (int s = 1; s <= 16; s++) {
        applyK<4><<<dim3(4, 8, NP), 256>>>(s - 1);
        reduceK<4><<<(NP * N * 4 / 4 + 255) / 256, 256>>>(s);
    }

    midK<<<NP, 256>>>(out);

    for (int s = 1; s <= 16; s++) {
        applyK<16><<<dim3(4, 8, NP), 256>>>(s - 1);
        reduceK<16><<<(NP * N * 16 / 4 + 255) / 256, 256>>>(s);
    }

    finalK<<<NP, 256>>>(out);
}

// round 3
// speedup vs baseline: 5.6380x; 1.0974x over previous
#include <cuda_runtime.h>

#define NP   16     // B*K problems
#define N    2048   // points per cloud
#define JC1  16     // j-chunks, chain 1 (CP=4)
#define JCH1 (N / JC1)
#define JC2  8      // j-chunks, chain 2 (CP=12)
#define JCH2 (N / JC2)

// ---------------- scratch (__device__ globals: allocation-free) ----------------
__device__ float4 g_Xs[NP][N];                  // scaled points + squared norm
__device__ float  g_deg[NP][N];                 // row degree of thresholded W
__device__ float  g_PT[NP][N][N];               // PT[p][j][i] = P[i][j] (transposed)
__device__ float  g_F[NP][N * 4];               // chain-1 t=0 (x,y,z,0)
__device__ float  g_U[NP][N * 12];              // chain-2 t=0 (first 12 cols of U)
__device__ float  g_p1[17][JC1][NP][N * 4];     // chain-1 per-step j-chunk partials
__device__ float  g_p2[17][JC2][NP][N * 12];    // chain-2 per-step j-chunk partials

// ---------------- helpers ----------------
__device__ __forceinline__ unsigned long long pack2(float a) {
    unsigned long long r;
    asm("mov.b64 %0, {%1, %1};" : "=l"(r) : "f"(a));
    return r;
}
__device__ __forceinline__ void fma2(unsigned long long& d, unsigned long long a,
                                     unsigned long long b) {
    asm("fma.rn.f32x2 %0, %1, %2, %0;" : "+l"(d) : "l"(a), "l"(b));
}
__device__ __forceinline__ float2 unpk(unsigned long long v) {
    float2 r;
    asm("mov.b64 {%0, %1}, %2;" : "=f"(r.x), "=f"(r.y) : "l"(v));
    return r;
}
__device__ __forceinline__ float warpSum(float v) {
#pragma unroll
    for (int o = 16; o; o >>= 1) v += __shfl_xor_sync(0xffffffffu, v, o);
    return v;
}

// ---------------- 1. scale points, init chain-1 state ----------------
__global__ void prepK(const float* __restrict__ pc, const float* __restrict__ al) {
    int idx = blockIdx.x * blockDim.x + threadIdx.x;
    if (idx >= NP * N) return;
    int p = idx / N, i = idx - p * N;
    int b = p >> 2, k = p & 3;
    const float* xp = pc + ((size_t)b * N + i) * 3;
    float x = xp[0] * al[k * 3 + 0];
    float y = xp[1] * al[k * 3 + 1];
    float z = xp[2] * al[k * 3 + 2];
    g_Xs[p][i] = make_float4(x, y, z, x * x + y * y + z * z);
    ((float4*)&g_F[p][0])[i] = make_float4(x, y, z, 0.f);
}

// ---------------- 2. degrees (row sums of thresholded W) ----------------
__global__ void degK() {
    int r = blockIdx.x * 8 + (threadIdx.x >> 5);   // one warp per row
    int lane = threadIdx.x & 31;
    int p = r / N, i = r - p * N;
    float4 xi = g_Xs[p][i];
    float s = 0.f;
    for (int j = lane; j < N; j += 32) {
        float4 xj = g_Xs[p][j];
        float d = xi.w + xj.w - 2.f * (xi.x * xj.x + xi.y * xj.y + xi.z * xj.z);
        float w = __expf(-d * 0.1f);
        s += (w < 0.1f) ? 0.f : w;
    }
    s = warpSum(s);
    if (lane == 0) g_deg[p][i] = s;
}

// ---------------- 3. build transposed lazy-walk matrix ----------------
__global__ void buildK() {
    int p = blockIdx.z;
    int i = blockIdx.x * 256 + threadIdx.x;
    int j0 = blockIdx.y * 8;
    float4 xi = g_Xs[p][i];
    float rd = 0.5f / g_deg[p][i];
#pragma unroll
    for (int jj = 0; jj < 8; jj++) {
        int j = j0 + jj;
        float4 xj = g_Xs[p][j];
        float d = xi.w + xj.w - 2.f * (xi.x * xj.x + xi.y * xj.y + xi.z * xj.z);
        float w = __expf(-d * 0.1f);
        w = (w < 0.1f) ? 0.f : w;
        g_PT[p][j][i] = w * rd + ((i == j) ? 0.5f : 0.f);
    }
}

// ---------------- 4a. chain-1 apply: partial(next) over a j-chunk (CP=4) --------
// Staging sums previous step's 16 partials (fused reduce). 4 rows/thread,
// LDG.128 on P (evict-first). Fixed summation order => deterministic.
__global__ void __launch_bounds__(256) apply1K(int sSrc, int sDst) {
    __shared__ __align__(16) float sc[JCH1 * 4];
    int p  = blockIdx.z;
    int jb = blockIdx.y * JCH1;
    int i0 = blockIdx.x * 1024 + threadIdx.x * 4;

    if (threadIdx.x < JCH1) {
        int t = threadIdx.x;
        float4 s;
        if (sSrc == 0) {
            s = ((const float4*)&g_F[p][0])[jb + t];
        } else {
            s = make_float4(0.f, 0.f, 0.f, 0.f);
#pragma unroll
            for (int jc = 0; jc < JC1; jc++) {
                float4 v = ((const float4*)&g_p1[sSrc][jc][p][0])[jb + t];
                s.x += v.x; s.y += v.y; s.z += v.z; s.w += v.w;
            }
        }
        ((float4*)sc)[t] = s;
    }
    __syncthreads();

    const float* PTp = &g_PT[p][0][0] + (size_t)jb * N;
    unsigned long long a[4][2];
#pragma unroll
    for (int r = 0; r < 4; r++) { a[r][0] = 0ull; a[r][1] = 0ull; }

#pragma unroll 4
    for (int j = 0; j < JCH1; j++) {
        float4 pv = __ldcs((const float4*)(PTp + (size_t)j * N + i0));
        const unsigned long long* cs = (const unsigned long long*)(sc + j * 4);
        unsigned long long c0 = cs[0], c1 = cs[1];
        unsigned long long px = pack2(pv.x), py = pack2(pv.y);
        unsigned long long pz = pack2(pv.z), pw = pack2(pv.w);
        fma2(a[0][0], px, c0); fma2(a[0][1], px, c1);
        fma2(a[1][0], py, c0); fma2(a[1][1], py, c1);
        fma2(a[2][0], pz, c0); fma2(a[2][1], pz, c1);
        fma2(a[3][0], pw, c0); fma2(a[3][1], pw, c1);
    }

    float4* o = (float4*)(&g_p1[sDst][blockIdx.y][p][0] + (size_t)i0 * 4);
#pragma unroll
    for (int r = 0; r < 4; r++) {
        float2 lo = unpk(a[r][0]), hi = unpk(a[r][1]);
        o[r] = make_float4(lo.x, lo.y, hi.x, hi.y);
    }
}

// ---------------- 4b. chain-2 apply: partial(next) over a j-chunk (CP=12) -------
__global__ void __launch_bounds__(256) apply2K(int sSrc, int sDst) {
    __shared__ __align__(16) float sc[JCH2 * 12];        // 12 KB
    int p  = blockIdx.z;
    int jb = blockIdx.y * JCH2;
    int i0 = blockIdx.x * 512 + threadIdx.x * 2;

    for (int t = threadIdx.x; t < JCH2 * 12 / 4; t += 256) {
        float4 s;
        if (sSrc == 0) {
            s = ((const float4*)&g_U[p][0])[jb * 3 + t];
        } else {
            s = make_float4(0.f, 0.f, 0.f, 0.f);
#pragma unroll
            for (int jc = 0; jc < JC2; jc++) {
                float4 v = ((const float4*)&g_p2[sSrc][jc][p][0])[jb * 3 + t];
                s.x += v.x; s.y += v.y; s.z += v.z; s.w += v.w;
            }
        }
        ((float4*)sc)[t] = s;
    }
    __syncthreads();

    const float* PTp = &g_PT[p][0][0] + (size_t)jb * N;
    unsigned long long a0[6], a1[6];
#pragma unroll
    for (int c = 0; c < 6; c++) { a0[c] = 0ull; a1[c] = 0ull; }

#pragma unroll 8
    for (int j = 0; j < JCH2; j++) {
        float2 pv = __ldcs((const float2*)(PTp + (size_t)j * N + i0));
        unsigned long long px = pack2(pv.x), py = pack2(pv.y);
        const unsigned long long* cs = (const unsigned long long*)(sc + j * 12);
#pragma unroll
        for (int c = 0; c < 6; c++) {
            unsigned long long cv = cs[c];
            fma2(a0[c], px, cv);
            fma2(a1[c], py, cv);
        }
    }

    float4* o = (float4*)(&g_p2[sDst][blockIdx.y][p][0] + (size_t)i0 * 12);
#pragma unroll
    for (int q = 0; q < 3; q++) {
        float2 e0 = unpk(a0[2 * q]), e1 = unpk(a0[2 * q + 1]);
        o[q] = make_float4(e0.x, e0.y, e1.x, e1.y);
    }
#pragma unroll
    for (int q = 0; q < 3; q++) {
        float2 e0 = unpk(a1[2 * q]), e1 = unpk(a1[2 * q + 1]);
        o[3 + q] = make_float4(e0.x, e0.y, e1.x, e1.y);
    }
}

// ---------------- 5. first-order features + build U + partial output ----------------
__global__ void midK(float* __restrict__ out) {
    int p = blockIdx.x, tid = threadIdx.x;
    const int slots[5] = {1, 2, 4, 8, 16};
    float ls[18];
#pragma unroll
    for (int v = 0; v < 18; v++) ls[v] = 0.f;

    for (int i = tid; i < N; i += 256) {
        float L[6][3];
        {
            float4 f0 = ((const float4*)&g_F[p][0])[i];
            L[0][0] = f0.x; L[0][1] = f0.y; L[0][2] = f0.z;
        }
#pragma unroll
        for (int s = 0; s < 5; s++) {
            float4 acc = make_float4(0.f, 0.f, 0.f, 0.f);
#pragma unroll
            for (int jc = 0; jc < JC1; jc++) {
                float4 v = ((const float4*)&g_p1[slots[s]][jc][p][0])[i];
                acc.x += v.x; acc.y += v.y; acc.z += v.z;
            }
            L[s + 1][0] = acc.x; L[s + 1][1] = acc.y; L[s + 1][2] = acc.z;
        }
        float* U = &g_U[p][i * 12];
#pragma unroll
        for (int c = 0; c < 3; c++) {
            float u0 = fabsf(L[0][c] - L[1][c]);
            float u1 = fabsf(L[1][c] - L[2][c]);
            float u2 = fabsf(L[2][c] - L[3][c]);
            float u3 = fabsf(L[3][c] - L[4][c]);
            float u4 = fabsf(L[4][c] - L[5][c]);
            U[c] = u0; U[3 + c] = u1; U[6 + c] = u2; U[9 + c] = u3;
            ls[c]      += L[5][c];
            ls[3 + c]  += u0;  ls[6 + c]  += u1;  ls[9 + c]  += u2;
            ls[12 + c] += u3;  ls[15 + c] += u4;
        }
    }
    __shared__ float red[18][8];
    int wid = tid >> 5, lane = tid & 31;
#pragma unroll
    for (int v = 0; v < 18; v++) {
        float s = warpSum(ls[v]);
        if (lane == 0) red[v][wid] = s;
    }
    __syncthreads();
    if (tid < 18) {
        float s = 0.f;
#pragma unroll
        for (int w = 0; w < 8; w++) s += red[tid][w];
        int b = p >> 2, k = p & 3;
        out[b * 192 + k * 48 + tid] = s * (1.f / 2048.f);
    }
}

// ---------------- 6. second-order features + remaining output ----------------
__global__ void finalK(float* __restrict__ out) {
    int p = blockIdx.x, tid = threadIdx.x;
    const int slots[5] = {1, 2, 4, 8, 16};
    float ls[30];
#pragma unroll
    for (int v = 0; v < 30; v++) ls[v] = 0.f;

    for (int i = tid; i < N; i += 256) {
        float A[5][12];
#pragma unroll
        for (int s = 0; s < 5; s++) {
#pragma unroll
            for (int q = 0; q < 3; q++) {
                float4 acc = make_float4(0.f, 0.f, 0.f, 0.f);
#pragma unroll
                for (int jc = 0; jc < JC2; jc++) {
                    float4 v = ((const float4*)&g_p2[slots[s]][jc][p][0])[i * 3 + q];
                    acc.x += v.x; acc.y += v.y; acc.z += v.z; acc.w += v.w;
                }
                A[s][4 * q + 0] = acc.x; A[s][4 * q + 1] = acc.y;
                A[s][4 * q + 2] = acc.z; A[s][4 * q + 3] = acc.w;
            }
        }
#pragma unroll
        for (int c = 0; c < 3;  c++) ls[c]      += fabsf(A[0][c] - A[1][c]);
#pragma unroll
        for (int c = 0; c < 6;  c++) ls[3 + c]  += fabsf(A[1][c] - A[2][c]);
#pragma unroll
        for (int c = 0; c < 9;  c++) ls[9 + c]  += fabsf(A[2][c] - A[3][c]);
#pragma unroll
        for (int c = 0; c < 12; c++) ls[18 + c] += fabsf(A[3][c] - A[4][c]);
    }
    __shared__ float red[30][8];
    int wid = tid >> 5, lane = tid & 31;
#pragma unroll
    for (int v = 0; v < 30; v++) {
        float s = warpSum(ls[v]);
        if (lane == 0) red[v][wid] = s;
    }
    __syncthreads();
    if (tid < 30) {
        float s = 0.f;
#pragma unroll
        for (int w = 0; w < 8; w++) s += red[tid][w];
        int b = p >> 2, k = p & 3;
        out[b * 192 + k * 48 + 18 + tid] = s * (1.f / 2048.f);
    }
}

// ---------------- launch ----------------
extern "C" void kernel_launch(void* const* d_in, const int* in_sizes, int n_in,
                              void* d_out, int out_size) {
    (void)in_sizes; (void)n_in; (void)out_size;
    const float* pc = (const float*)d_in[0];   // [4,2048,3]
    const float* al = (const float*)d_in[1];   // [4,3]
    float* out = (float*)d_out;                // [768]

    prepK<<<(NP * N + 255) / 256, 256>>>(pc, al);
    degK<<<NP * N / 8, 256>>>();
    buildK<<<dim3(N / 256, N / 8, NP), 256>>>();

    for (int s = 1; s <= 16; s++)
        apply1K<<<dim3(2, JC1, NP), 256>>>(s - 1, s);

    midK<<<NP, 256>>>(out);

    for (int s = 1; s <= 16; s++)
        apply2K<<<dim3(4, JC2, NP), 256>>>(s - 1, s);

    finalK<<<NP, 256>>>(out);
}